// round 1
// baseline (speedup 1.0000x reference)
#include <cuda_runtime.h>
#include <cuda_fp16.h>
#include <cstdint>
#include <cstddef>

#define BATCH     131072
#define FDIM      512
#define F2DIM     256
#define OBJ_DIM   100000
#define PRED_DIM  2000
#define EPS_F     1e-5f

// ---------------- device scratch (static, no allocation) ----------------
__device__ int   d_cnt_s[OBJ_DIM];
__device__ int   d_cnt_o[OBJ_DIM];
__device__ int   d_cnt_p[PRED_DIM];
__device__ __align__(16) float  d_sumb[3][FDIM];
__device__ __align__(16) float  d_sqb [3][FDIM];
__device__ __align__(16) float  d_cA  [3][FDIM];   // BN-relu affine: a
__device__ __align__(16) float  d_cC  [3][FDIM];   // BN-relu affine: c
__device__ __align__(16) __half d_W4hh[F2DIM * FDIM];  // W4 hi half
__device__ __align__(16) __half d_W4hl[F2DIM * FDIM];  // W4 residual half
__device__ __align__(16) float  d_y[(size_t)BATCH * F2DIM];  // 128 MB pre-BN layer-4 output
__device__ float d_sum4[F2DIM];
__device__ float d_sq4 [F2DIM];

// ---------------- kernel 1: zero scratch ----------------
__global__ void k_zero() {
    int i = blockIdx.x * blockDim.x + threadIdx.x;
    int n = gridDim.x * blockDim.x;
    for (int j = i; j < OBJ_DIM; j += n) { d_cnt_s[j] = 0; d_cnt_o[j] = 0; }
    for (int j = i; j < PRED_DIM; j += n) d_cnt_p[j] = 0;
    if (i < FDIM) {
        #pragma unroll
        for (int b = 0; b < 3; b++) { d_sumb[b][i] = 0.f; d_sqb[b][i] = 0.f; }
    }
    if (i < F2DIM) { d_sum4[i] = 0.f; d_sq4[i] = 0.f; }
}

// ---------------- kernel 2: index histograms ----------------
__global__ void k_hist(const int* __restrict__ subj, const int* __restrict__ obj,
                       const int* __restrict__ predi) {
    int i = blockIdx.x * blockDim.x + threadIdx.x;
    if (i < BATCH) {
        atomicAdd(&d_cnt_s[subj[i]], 1);
        atomicAdd(&d_cnt_o[obj[i]], 1);
        atomicAdd(&d_cnt_p[predi[i]], 1);
    }
}

// ---------------- kernel 3: count-weighted column stats of a table ----------------
__global__ void __launch_bounds__(128) k_colstats(const float* __restrict__ W,
                                                  int cntSel, int R, int outSel) {
    const int t = threadIdx.x;                    // 128 threads -> 4 cols each (float4)
    const int* cnt = (cntSel == 0) ? d_cnt_s : (cntSel == 1) ? d_cnt_o : d_cnt_p;
    float4 s = make_float4(0.f, 0.f, 0.f, 0.f);
    float4 q = make_float4(0.f, 0.f, 0.f, 0.f);
    for (int r = blockIdx.x; r < R; r += gridDim.x) {
        int c = cnt[r];
        if (c) {
            float fc = (float)c;
            float4 v = __ldg((const float4*)(W + (size_t)r * FDIM) + t);
            s.x += fc * v.x; s.y += fc * v.y; s.z += fc * v.z; s.w += fc * v.w;
            q.x += fc * v.x * v.x; q.y += fc * v.y * v.y;
            q.z += fc * v.z * v.z; q.w += fc * v.w * v.w;
        }
    }
    int c0 = t * 4;
    atomicAdd(&d_sumb[outSel][c0 + 0], s.x);
    atomicAdd(&d_sumb[outSel][c0 + 1], s.y);
    atomicAdd(&d_sumb[outSel][c0 + 2], s.z);
    atomicAdd(&d_sumb[outSel][c0 + 3], s.w);
    atomicAdd(&d_sqb[outSel][c0 + 0], q.x);
    atomicAdd(&d_sqb[outSel][c0 + 1], q.y);
    atomicAdd(&d_sqb[outSel][c0 + 2], q.z);
    atomicAdd(&d_sqb[outSel][c0 + 3], q.w);
}

// ---------------- kernel 4: branch BN-relu affine coefficients ----------------
// BN(x+b) = g*(x - mean_x)*rsqrt(var+eps) + be  (bias b cancels)
__global__ void k_coef(const float* __restrict__ g1, const float* __restrict__ be1,
                       const float* __restrict__ g2, const float* __restrict__ be2,
                       const float* __restrict__ g3, const float* __restrict__ be3) {
    int t = threadIdx.x;  // 512
    const float* G[3]  = {g1, g2, g3};
    const float* BE[3] = {be1, be2, be3};
    #pragma unroll
    for (int b = 0; b < 3; b++) {
        float m = d_sumb[b][t] * (1.0f / BATCH);
        float v = d_sqb[b][t] * (1.0f / BATCH) - m * m;
        float a = G[b][t] * rsqrtf(v + EPS_F);
        d_cA[b][t] = a;
        d_cC[b][t] = BE[b][t] - a * m;
    }
}

// ---------------- kernel 5: W4 -> fp16 hi/lo split ----------------
__global__ void k_w4(const float* __restrict__ W4) {
    int i = blockIdx.x * blockDim.x + threadIdx.x;
    float w = W4[i];
    __half hi = __float2half_rn(w);
    float lo = w - __half2float(hi);
    d_W4hh[i] = hi;
    d_W4hl[i] = __float2half_rn(lo);
}

// ---------------- kernel 6: fused gather + branch BN-relu + GEMM + stats ----------------
#define ROWS 64
#define SA   520          // A smem stride in halfs (1040 B, bank-shift 4 -> conflict free)
#define KC   32
#define SB   40           // B smem stride in halfs (80 B, bank-shift 20 -> conflict free)

#define SM_A_BYTES  (ROWS * SA * 2)          // 66560
#define SM_BH_OFF   (SM_A_BYTES)
#define SM_BL_OFF   (SM_BH_OFF + F2DIM * SB * 2)   // +20480
#define SM_CS_OFF   (SM_BL_OFF + F2DIM * SB * 2)   // +20480
#define SM_CQ_OFF   (SM_CS_OFF + F2DIM * 4)
#define SM_IDX_OFF  (SM_CQ_OFF + F2DIM * 4)
#define SM_TOTAL    (SM_IDX_OFF + 3 * ROWS * 4)    // 110336 bytes

__global__ void __launch_bounds__(256, 2) k_main(
    const int* __restrict__ subj, const int* __restrict__ obj, const int* __restrict__ predi,
    const float* __restrict__ W1, const float* __restrict__ W2, const float* __restrict__ W3)
{
    extern __shared__ char sm[];
    __half* As     = (__half*)sm;
    __half* Bhi    = (__half*)(sm + SM_BH_OFF);
    __half* Blo    = (__half*)(sm + SM_BL_OFF);
    float*  colsum = (float*)(sm + SM_CS_OFF);
    float*  colsq  = (float*)(sm + SM_CQ_OFF);
    int*    idxs   = (int*)(sm + SM_IDX_OFF);

    const int tid  = threadIdx.x;
    const int lane = tid & 31;
    const int wid  = tid >> 5;
    const int i0   = blockIdx.x * ROWS;

    if (tid < ROWS) {
        idxs[tid]            = subj[i0 + tid];
        idxs[ROWS + tid]     = obj[i0 + tid];
        idxs[2 * ROWS + tid] = predi[i0 + tid];
    }
    if (tid < F2DIM) { colsum[tid] = 0.f; colsq[tid] = 0.f; }
    __syncthreads();

    // ---- phase 1: gather + branch BN-relu + sum -> fp16 A tile ----
    #pragma unroll 1
    for (int rr = 0; rr < 8; rr++) {
        int row = wid * 8 + rr;
        int s = idxs[row], o = idxs[ROWS + row], p = idxs[2 * ROWS + row];
        const float4* r1 = (const float4*)(W1 + (size_t)s * FDIM);
        const float4* r2 = (const float4*)(W2 + (size_t)o * FDIM);
        const float4* r3 = (const float4*)(W3 + (size_t)p * FDIM);
        #pragma unroll
        for (int j = 0; j < 4; j++) {
            int e = j * 32 + lane;
            float4 w1 = __ldg(r1 + e);
            float4 w2 = __ldg(r2 + e);
            float4 w3 = __ldg(r3 + e);
            int k0 = e * 4;
            float4 A1 = *(const float4*)&d_cA[0][k0];
            float4 C1 = *(const float4*)&d_cC[0][k0];
            float4 A2 = *(const float4*)&d_cA[1][k0];
            float4 C2 = *(const float4*)&d_cC[1][k0];
            float4 A3 = *(const float4*)&d_cA[2][k0];
            float4 C3 = *(const float4*)&d_cC[2][k0];
            float f0 = fmaxf(fmaf(A1.x, w1.x, C1.x), 0.f) + fmaxf(fmaf(A2.x, w2.x, C2.x), 0.f) + fmaxf(fmaf(A3.x, w3.x, C3.x), 0.f);
            float f1 = fmaxf(fmaf(A1.y, w1.y, C1.y), 0.f) + fmaxf(fmaf(A2.y, w2.y, C2.y), 0.f) + fmaxf(fmaf(A3.y, w3.y, C3.y), 0.f);
            float f2 = fmaxf(fmaf(A1.z, w1.z, C1.z), 0.f) + fmaxf(fmaf(A2.z, w2.z, C2.z), 0.f) + fmaxf(fmaf(A3.z, w3.z, C3.z), 0.f);
            float f3 = fmaxf(fmaf(A1.w, w1.w, C1.w), 0.f) + fmaxf(fmaf(A2.w, w2.w, C2.w), 0.f) + fmaxf(fmaf(A3.w, w3.w, C3.w), 0.f);
            __half2* dst = (__half2*)(As + row * SA + k0);
            dst[0] = __floats2half2_rn(f0, f1);
            dst[1] = __floats2half2_rn(f2, f3);
        }
    }
    __syncthreads();

    // ---- phase 2: GEMM  y[64x256] = A[64x512] * W4^T  via mma.sync f16 (W4 hi+lo) ----
    const int wm  = wid >> 2;    // 0..1 -> 32-row strip
    const int wn  = wid & 3;     // 0..3 -> 64-col strip
    const int g   = lane >> 2;   // group id
    const int tig = lane & 3;    // thread in group

    float acc[2][8][4];
    #pragma unroll
    for (int mt = 0; mt < 2; mt++)
        #pragma unroll
        for (int nt = 0; nt < 8; nt++)
            #pragma unroll
            for (int u = 0; u < 4; u++) acc[mt][nt][u] = 0.f;

    #pragma unroll 1
    for (int kc = 0; kc < FDIM; kc += KC) {
        // stage W4 chunk (hi+lo): thread tid = output col n
        {
            const uint4* sh = (const uint4*)(d_W4hh + tid * FDIM + kc);
            const uint4* sl = (const uint4*)(d_W4hl + tid * FDIM + kc);
            uint4* dh = (uint4*)(Bhi + tid * SB);
            uint4* dl = (uint4*)(Blo + tid * SB);
            #pragma unroll
            for (int u = 0; u < 4; u++) { dh[u] = sh[u]; dl[u] = sl[u]; }
        }
        __syncthreads();
        #pragma unroll
        for (int ks = 0; ks < KC; ks += 16) {
            unsigned a[2][4];
            #pragma unroll
            for (int mt = 0; mt < 2; mt++) {
                const __half* ap = As + (wm * 32 + mt * 16 + g) * SA + (kc + ks) + tig * 2;
                a[mt][0] = *(const unsigned*)(ap);
                a[mt][1] = *(const unsigned*)(ap + 8 * SA);
                a[mt][2] = *(const unsigned*)(ap + 8);
                a[mt][3] = *(const unsigned*)(ap + 8 * SA + 8);
            }
            #pragma unroll
            for (int nt = 0; nt < 8; nt++) {
                int n = wn * 64 + nt * 8 + g;
                const __half* bph = Bhi + n * SB + ks + tig * 2;
                const __half* bpl = Blo + n * SB + ks + tig * 2;
                unsigned bh0 = *(const unsigned*)(bph);
                unsigned bh1 = *(const unsigned*)(bph + 8);
                unsigned bl0 = *(const unsigned*)(bpl);
                unsigned bl1 = *(const unsigned*)(bpl + 8);
                #pragma unroll
                for (int mt = 0; mt < 2; mt++) {
                    asm volatile(
                        "mma.sync.aligned.m16n8k16.row.col.f32.f16.f16.f32 "
                        "{%0,%1,%2,%3}, {%4,%5,%6,%7}, {%8,%9}, {%0,%1,%2,%3};\n"
                        : "+f"(acc[mt][nt][0]), "+f"(acc[mt][nt][1]),
                          "+f"(acc[mt][nt][2]), "+f"(acc[mt][nt][3])
                        : "r"(a[mt][0]), "r"(a[mt][1]), "r"(a[mt][2]), "r"(a[mt][3]),
                          "r"(bh0), "r"(bh1));
                    asm volatile(
                        "mma.sync.aligned.m16n8k16.row.col.f32.f16.f16.f32 "
                        "{%0,%1,%2,%3}, {%4,%5,%6,%7}, {%8,%9}, {%0,%1,%2,%3};\n"
                        : "+f"(acc[mt][nt][0]), "+f"(acc[mt][nt][1]),
                          "+f"(acc[mt][nt][2]), "+f"(acc[mt][nt][3])
                        : "r"(a[mt][0]), "r"(a[mt][1]), "r"(a[mt][2]), "r"(a[mt][3]),
                          "r"(bl0), "r"(bl1));
                }
            }
        }
        __syncthreads();
    }

    // ---- phase 3: store y (fp32) + column sum/sumsq ----
    #pragma unroll
    for (int nt = 0; nt < 8; nt++) {
        int col = wn * 64 + nt * 8 + tig * 2;
        float s0 = 0.f, s1 = 0.f, q0 = 0.f, q1 = 0.f;
        #pragma unroll
        for (int mt = 0; mt < 2; mt++) {
            float c0 = acc[mt][nt][0], c1 = acc[mt][nt][1];
            float c2 = acc[mt][nt][2], c3 = acc[mt][nt][3];
            int r = i0 + wm * 32 + mt * 16 + g;
            *(float2*)(d_y + (size_t)r * F2DIM + col)       = make_float2(c0, c1);
            *(float2*)(d_y + (size_t)(r + 8) * F2DIM + col) = make_float2(c2, c3);
            s0 += c0 + c2;  s1 += c1 + c3;
            q0 += c0 * c0 + c2 * c2;  q1 += c1 * c1 + c3 * c3;
        }
        #pragma unroll
        for (int off = 4; off < 32; off <<= 1) {
            s0 += __shfl_xor_sync(0xffffffffu, s0, off);
            s1 += __shfl_xor_sync(0xffffffffu, s1, off);
            q0 += __shfl_xor_sync(0xffffffffu, q0, off);
            q1 += __shfl_xor_sync(0xffffffffu, q1, off);
        }
        if (lane < 4) {
            atomicAdd(&colsum[col], s0);
            atomicAdd(&colsum[col + 1], s1);
            atomicAdd(&colsq[col], q0);
            atomicAdd(&colsq[col + 1], q1);
        }
    }
    __syncthreads();
    if (tid < F2DIM) {
        atomicAdd(&d_sum4[tid], colsum[tid]);
        atomicAdd(&d_sq4[tid], colsq[tid]);
    }
}

// ---------------- kernel 7: BN4 + relu + W5 dot -> logits ----------------
__global__ void __launch_bounds__(256) k_final(
    const float* __restrict__ g4, const float* __restrict__ be4,
    const float* __restrict__ W5, const float* __restrict__ b5,
    float* __restrict__ out)
{
    const int lane = threadIdx.x & 31;
    const int wid  = threadIdx.x >> 5;
    float a[8], c[8], w[8];
    #pragma unroll
    for (int j = 0; j < 8; j++) {
        int col = lane * 8 + j;
        float m  = d_sum4[col] * (1.0f / BATCH);
        float v  = d_sq4[col] * (1.0f / BATCH) - m * m;
        float aa = g4[col] * rsqrtf(v + EPS_F);
        a[j] = aa;
        c[j] = be4[col] - aa * m;
        w[j] = W5[col];
    }
    float bias = b5[0];
    for (int i = blockIdx.x * 8 + wid; i < BATCH; i += gridDim.x * 8) {
        const float4* yp = (const float4*)(d_y + (size_t)i * F2DIM + lane * 8);
        float4 v0 = yp[0];
        float4 v1 = yp[1];
        float accv =
            fmaxf(fmaf(a[0], v0.x, c[0]), 0.f) * w[0] +
            fmaxf(fmaf(a[1], v0.y, c[1]), 0.f) * w[1] +
            fmaxf(fmaf(a[2], v0.z, c[2]), 0.f) * w[2] +
            fmaxf(fmaf(a[3], v0.w, c[3]), 0.f) * w[3] +
            fmaxf(fmaf(a[4], v1.x, c[4]), 0.f) * w[4] +
            fmaxf(fmaf(a[5], v1.y, c[5]), 0.f) * w[5] +
            fmaxf(fmaf(a[6], v1.z, c[6]), 0.f) * w[6] +
            fmaxf(fmaf(a[7], v1.w, c[7]), 0.f) * w[7];
        #pragma unroll
        for (int off = 16; off; off >>= 1)
            accv += __shfl_xor_sync(0xffffffffu, accv, off);
        if (lane == 0) out[i] = accv + bias;
    }
}

// ---------------- launch ----------------
extern "C" void kernel_launch(void* const* d_in, const int* in_sizes, int n_in,
                              void* d_out, int out_size)
{
    (void)in_sizes; (void)n_in; (void)out_size;
    const int*   subj  = (const int*)d_in[0];
    const int*   obj   = (const int*)d_in[1];
    const int*   predi = (const int*)d_in[2];
    const float* W1    = (const float*)d_in[3];
    const float* g1    = (const float*)d_in[5];
    const float* be1   = (const float*)d_in[6];
    const float* W2    = (const float*)d_in[7];
    const float* g2    = (const float*)d_in[9];
    const float* be2   = (const float*)d_in[10];
    const float* W3    = (const float*)d_in[11];
    const float* g3    = (const float*)d_in[13];
    const float* be3   = (const float*)d_in[14];
    const float* W4    = (const float*)d_in[15];
    const float* g4    = (const float*)d_in[17];
    const float* be4   = (const float*)d_in[18];
    const float* W5    = (const float*)d_in[19];
    const float* b5    = (const float*)d_in[20];
    float* out = (float*)d_out;

    cudaFuncSetAttribute(k_main, cudaFuncAttributeMaxDynamicSharedMemorySize, SM_TOTAL);

    k_zero<<<256, 256>>>();
    k_hist<<<BATCH / 256, 256>>>(subj, obj, predi);
    k_colstats<<<1184, 128>>>(W1, 0, OBJ_DIM, 0);
    k_colstats<<<1184, 128>>>(W2, 1, OBJ_DIM, 1);
    k_colstats<<<128, 128>>>(W3, 2, PRED_DIM, 2);
    k_coef<<<1, 512>>>(g1, be1, g2, be2, g3, be3);
    k_w4<<<(F2DIM * FDIM) / 256, 256>>>(W4);
    k_main<<<BATCH / ROWS, 256, SM_TOTAL>>>(subj, obj, predi, W1, W2, W3);
    k_final<<<2048, 256>>>(g4, be4, W5, b5, out);
}

// round 3
// speedup vs baseline: 1.9944x; 1.9944x over previous
#include <cuda_runtime.h>
#include <cuda_fp16.h>
#include <cstdint>
#include <cstddef>

#define BATCH     131072
#define FDIM      512
#define F2DIM     256
#define OBJ_DIM   100000
#define PRED_DIM  2000
#define EPS_F     1e-5f

// ---------------- device scratch (static, no allocation) ----------------
__device__ int   d_cnt_s[OBJ_DIM];
__device__ int   d_cnt_o[OBJ_DIM];
__device__ int   d_cnt_p[PRED_DIM];
__device__ int   d_ns, d_no, d_np;
__device__ __align__(16) int2  d_list_s[OBJ_DIM];
__device__ __align__(16) int2  d_list_o[OBJ_DIM];
__device__ __align__(16) int2  d_list_p[PRED_DIM];
__device__ __align__(16) float d_sumb[3][FDIM];
__device__ __align__(16) float d_sqb [3][FDIM];
__device__ __align__(16) __half d_W4hh[F2DIM * FDIM];   // row-major [256][512]
__device__ __align__(16) __half d_W4hl[F2DIM * FDIM];
__device__ __align__(16) __half d_Af[(size_t)BATCH * FDIM];  // fused fp16 A, 128 MB
__device__ __align__(16) float d_y[(size_t)BATCH * F2DIM];   // pre-BN layer-4 out, 128 MB
__device__ float d_sum4[F2DIM];
__device__ float d_sq4 [F2DIM];

// ---------------- helpers ----------------
__device__ __forceinline__ uint32_t smem_u32(const void* p) {
    uint32_t a;
    asm("{ .reg .u64 t; cvta.to.shared.u64 t, %1; cvt.u32.u64 %0, t; }" : "=r"(a) : "l"(p));
    return a;
}
__device__ __forceinline__ void cp16(uint32_t dst, const void* src) {
    asm volatile("cp.async.cg.shared.global [%0], [%1], 16;" :: "r"(dst), "l"(src) : "memory");
}
__device__ __forceinline__ void cp_commit() {
    asm volatile("cp.async.commit_group;" ::: "memory");
}
__device__ __forceinline__ void cp_wait0() {
    asm volatile("cp.async.wait_group 0;" ::: "memory");
}
__device__ __forceinline__ float relu_aff(float a, float w, float c) {
    return fmaxf(fmaf(a, w, c), 0.f);
}

// ---------------- kernel 0: zero scratch + W4 fp16 hi/lo split ----------------
__global__ void __launch_bounds__(256) k_zero(const float* __restrict__ W4) {
    int i = blockIdx.x * blockDim.x + threadIdx.x;   // grid 512*256 = 131072
    if (i < OBJ_DIM) { d_cnt_s[i] = 0; d_cnt_o[i] = 0; }
    if (i < PRED_DIM) d_cnt_p[i] = 0;
    if (i == 0) { d_ns = 0; d_no = 0; d_np = 0; }
    if (i < FDIM) {
        #pragma unroll
        for (int b = 0; b < 3; b++) { d_sumb[b][i] = 0.f; d_sqb[b][i] = 0.f; }
    }
    if (i < F2DIM) { d_sum4[i] = 0.f; d_sq4[i] = 0.f; }
    {
        float w = W4[i];
        __half hi = __float2half_rn(w);
        float lo = w - __half2float(hi);
        d_W4hh[i] = hi;
        d_W4hl[i] = __float2half_rn(lo);
    }
}

// ---------------- kernel 1: index histograms ----------------
__global__ void k_hist(const int* __restrict__ subj, const int* __restrict__ obj,
                       const int* __restrict__ predi) {
    int i = blockIdx.x * blockDim.x + threadIdx.x;
    if (i < BATCH) {
        atomicAdd(&d_cnt_s[subj[i]], 1);
        atomicAdd(&d_cnt_o[obj[i]], 1);
        atomicAdd(&d_cnt_p[predi[i]], 1);
    }
}

// ---------------- kernel 2: compact nonzero (row,count) lists ----------------
__global__ void k_compact() {
    int i = blockIdx.x * blockDim.x + threadIdx.x;
    if (i < OBJ_DIM) {
        int c = d_cnt_s[i];
        if (c) { int p = atomicAdd(&d_ns, 1); d_list_s[p] = make_int2(i, c); }
        c = d_cnt_o[i];
        if (c) { int p = atomicAdd(&d_no, 1); d_list_o[p] = make_int2(i, c); }
    }
    if (i < PRED_DIM) {
        int c = d_cnt_p[i];
        if (c) { int p = atomicAdd(&d_np, 1); d_list_p[p] = make_int2(i, c); }
    }
}

// ---------------- kernel 3: count-weighted column stats (all 3 tables, one launch) ----------------
__global__ void __launch_bounds__(128) k_cs(const float* __restrict__ W1,
                                            const float* __restrict__ W2,
                                            const float* __restrict__ W3,
                                            int split1, int split2) {
    __shared__ int2 ent[64];
    const float* W;
    int sel, bid, nblk;
    if ((int)blockIdx.x < split1)      { W = W1; sel = 0; bid = blockIdx.x;          nblk = split1; }
    else if ((int)blockIdx.x < split2) { W = W2; sel = 1; bid = blockIdx.x - split1; nblk = split2 - split1; }
    else                               { W = W3; sel = 2; bid = blockIdx.x - split2; nblk = gridDim.x - split2; }
    const int2* L = (sel == 0) ? d_list_s : (sel == 1) ? d_list_o : d_list_p;
    const int* nP = (sel == 0) ? &d_ns : (sel == 1) ? &d_no : &d_np;
    int total = *nP;
    int t = threadIdx.x;
    float4 s = make_float4(0.f, 0.f, 0.f, 0.f);
    float4 q = make_float4(0.f, 0.f, 0.f, 0.f);
    for (int base = bid * 64; base < total; base += nblk * 64) {
        __syncthreads();
        if (t < 64) {
            int ii = base + t;
            ent[t] = (ii < total) ? L[ii] : make_int2(0, 0);
        }
        __syncthreads();
        int n = min(64, total - base);
        for (int ii = 0; ii < n; ii += 4) {
            int2 e0 = ent[ii];
            int2 e1 = ent[ii + 1 < n ? ii + 1 : ii];
            int2 e2 = ent[ii + 2 < n ? ii + 2 : ii];
            int2 e3 = ent[ii + 3 < n ? ii + 3 : ii];
            float c0 = (float)e0.y;
            float c1 = (ii + 1 < n) ? (float)e1.y : 0.f;
            float c2 = (ii + 2 < n) ? (float)e2.y : 0.f;
            float c3 = (ii + 3 < n) ? (float)e3.y : 0.f;
            float4 v0 = __ldg((const float4*)(W + (size_t)e0.x * FDIM) + t);
            float4 v1 = __ldg((const float4*)(W + (size_t)e1.x * FDIM) + t);
            float4 v2 = __ldg((const float4*)(W + (size_t)e2.x * FDIM) + t);
            float4 v3 = __ldg((const float4*)(W + (size_t)e3.x * FDIM) + t);
            s.x += c0 * v0.x + c1 * v1.x + c2 * v2.x + c3 * v3.x;
            s.y += c0 * v0.y + c1 * v1.y + c2 * v2.y + c3 * v3.y;
            s.z += c0 * v0.z + c1 * v1.z + c2 * v2.z + c3 * v3.z;
            s.w += c0 * v0.w + c1 * v1.w + c2 * v2.w + c3 * v3.w;
            q.x += c0 * v0.x * v0.x + c1 * v1.x * v1.x + c2 * v2.x * v2.x + c3 * v3.x * v3.x;
            q.y += c0 * v0.y * v0.y + c1 * v1.y * v1.y + c2 * v2.y * v2.y + c3 * v3.y * v3.y;
            q.z += c0 * v0.z * v0.z + c1 * v1.z * v1.z + c2 * v2.z * v2.z + c3 * v3.z * v3.z;
            q.w += c0 * v0.w * v0.w + c1 * v1.w * v1.w + c2 * v2.w * v2.w + c3 * v3.w * v3.w;
        }
    }
    int c0 = t * 4;
    atomicAdd(&d_sumb[sel][c0 + 0], s.x);
    atomicAdd(&d_sumb[sel][c0 + 1], s.y);
    atomicAdd(&d_sumb[sel][c0 + 2], s.z);
    atomicAdd(&d_sumb[sel][c0 + 3], s.w);
    atomicAdd(&d_sqb[sel][c0 + 0], q.x);
    atomicAdd(&d_sqb[sel][c0 + 1], q.y);
    atomicAdd(&d_sqb[sel][c0 + 2], q.z);
    atomicAdd(&d_sqb[sel][c0 + 3], q.w);
}

// ---------------- kernel 4: gather + branch BN-relu + sum -> fp16 A (gmem) ----------------
// 32 rows/block (8 warps x 4 rows). Low regs, high occupancy, MLP 12 per row-iter.
__global__ void __launch_bounds__(256) k_gather(
    const int* __restrict__ subj, const int* __restrict__ obj, const int* __restrict__ predi,
    const float* __restrict__ W1, const float* __restrict__ W2, const float* __restrict__ W3,
    const float* __restrict__ g1, const float* __restrict__ be1,
    const float* __restrict__ g2, const float* __restrict__ be2,
    const float* __restrict__ g3, const float* __restrict__ be3)
{
    __shared__ float cA[3 * FDIM];
    __shared__ float cC[3 * FDIM];
    const int tid = threadIdx.x, lane = tid & 31, wid = tid >> 5;
    for (int t = tid; t < FDIM; t += 256) {
        float m, v, a;
        m = d_sumb[0][t] * (1.f / BATCH); v = d_sqb[0][t] * (1.f / BATCH) - m * m;
        a = g1[t] * rsqrtf(v + EPS_F); cA[t] = a;          cC[t] = be1[t] - a * m;
        m = d_sumb[1][t] * (1.f / BATCH); v = d_sqb[1][t] * (1.f / BATCH) - m * m;
        a = g2[t] * rsqrtf(v + EPS_F); cA[512 + t] = a;    cC[512 + t] = be2[t] - a * m;
        m = d_sumb[2][t] * (1.f / BATCH); v = d_sqb[2][t] * (1.f / BATCH) - m * m;
        a = g3[t] * rsqrtf(v + EPS_F); cA[1024 + t] = a;   cC[1024 + t] = be3[t] - a * m;
    }
    __syncthreads();

    const int r0 = blockIdx.x * 32 + wid * 4;
    int sx[4], ox[4], px[4];
    #pragma unroll
    for (int rr = 0; rr < 4; rr++) {
        sx[rr] = subj[r0 + rr];
        ox[rr] = obj[r0 + rr];
        px[rr] = predi[r0 + rr];
    }
    #pragma unroll 1
    for (int rr = 0; rr < 4; rr++) {
        const int r = r0 + rr;
        const float4* p1 = (const float4*)(W1 + (size_t)sx[rr] * FDIM);
        const float4* p2 = (const float4*)(W2 + (size_t)ox[rr] * FDIM);
        const float4* p3 = (const float4*)(W3 + (size_t)px[rr] * FDIM);
        float4 L1[4], L2[4], L3[4];
        #pragma unroll
        for (int j = 0; j < 4; j++) {
            int e = j * 32 + lane;
            L1[j] = __ldg(p1 + e);
            L2[j] = __ldg(p2 + e);
            L3[j] = __ldg(p3 + e);
        }
        #pragma unroll
        for (int j = 0; j < 4; j++) {
            int e = j * 32 + lane;
            int k0 = e * 4;
            float4 A1 = *(const float4*)&cA[k0],        C1 = *(const float4*)&cC[k0];
            float4 A2 = *(const float4*)&cA[512 + k0],  C2 = *(const float4*)&cC[512 + k0];
            float4 A3 = *(const float4*)&cA[1024 + k0], C3 = *(const float4*)&cC[1024 + k0];
            float f0 = relu_aff(A1.x, L1[j].x, C1.x) + relu_aff(A2.x, L2[j].x, C2.x) + relu_aff(A3.x, L3[j].x, C3.x);
            float f1 = relu_aff(A1.y, L1[j].y, C1.y) + relu_aff(A2.y, L2[j].y, C2.y) + relu_aff(A3.y, L3[j].y, C3.y);
            float f2 = relu_aff(A1.z, L1[j].z, C1.z) + relu_aff(A2.z, L2[j].z, C2.z) + relu_aff(A3.z, L3[j].z, C3.z);
            float f3 = relu_aff(A1.w, L1[j].w, C1.w) + relu_aff(A2.w, L2[j].w, C2.w) + relu_aff(A3.w, L3[j].w, C3.w);
            __half2 h0 = __floats2half2_rn(f0, f1);
            __half2 h1 = __floats2half2_rn(f2, f3);
            uint2 u;
            u.x = *(unsigned*)&h0;
            u.y = *(unsigned*)&h1;
            *(uint2*)(d_Af + (size_t)r * FDIM + k0) = u;
        }
    }
}

// ---------------- kernel 5: GEMM y = A * W4^T (fp16 hi/lo, cp.async pipelined) ----------------
// Tile 128x256, 512 threads (16 warps: wm 0..3 = 32-row strip, wn 0..3 = 64-col strip).
#define KC      64
#define SROW    144                         // smem row stride bytes (72 halfs)
#define AS_ST   (128 * SROW)                // 18432 per stage
#define SM_BH   (2 * AS_ST)                 // 36864
#define BH_ST   (F2DIM * SROW)              // 36864 per stage
#define SM_BL   (SM_BH + 2 * BH_ST)         // 110592
#define SM_SUM  (SM_BL + 2 * BH_ST)         // 184320
#define SM_SQ   (SM_SUM + 1024)
#define SM_TOT  (SM_SQ + 1024)              // 186368

__device__ __forceinline__ void gemm_issue(uint32_t smb, int i0, int c) {
    const int tid = threadIdx.x;
    const int s = c & 1;
    // A: 128 rows x 64 halfs
    {
        const __half* Ag = d_Af + (size_t)i0 * FDIM + c * KC;
        #pragma unroll
        for (int u = 0; u < 2; u++) {
            int idx = tid + 512 * u;
            int row = idx >> 3, o = idx & 7;
            cp16(smb + s * AS_ST + row * SROW + o * 16, Ag + (size_t)row * FDIM + o * 8);
        }
    }
    // B hi + lo: 256 rows x 64 halfs each
    #pragma unroll
    for (int u = 0; u < 4; u++) {
        int idx = tid + 512 * u;
        int n = idx >> 3, o = idx & 7;
        cp16(smb + SM_BH + s * BH_ST + n * SROW + o * 16, d_W4hh + n * FDIM + c * KC + o * 8);
        cp16(smb + SM_BL + s * BH_ST + n * SROW + o * 16, d_W4hl + n * FDIM + c * KC + o * 8);
    }
}

__global__ void __launch_bounds__(512, 1) k_gemm() {
    extern __shared__ char sm[];
    const uint32_t smb = smem_u32(sm);
    const int tid = threadIdx.x, lane = tid & 31, wid = tid >> 5;
    const int i0 = blockIdx.x * 128;
    float* colsum = (float*)(sm + SM_SUM);
    float* colsq  = (float*)(sm + SM_SQ);
    if (tid < 256) colsum[tid] = 0.f;
    else colsq[tid - 256] = 0.f;

    const int wm = wid >> 2, wn = wid & 3, g = lane >> 2, tig = lane & 3;

    float acc[2][8][4];
    #pragma unroll
    for (int mt = 0; mt < 2; mt++)
        #pragma unroll
        for (int nt = 0; nt < 8; nt++)
            #pragma unroll
            for (int u = 0; u < 4; u++) acc[mt][nt][u] = 0.f;

    gemm_issue(smb, i0, 0);
    cp_commit();

    #pragma unroll 1
    for (int c = 0; c < 8; c++) {
        cp_wait0();
        __syncthreads();
        if (c < 7) { gemm_issue(smb, i0, c + 1); cp_commit(); }
        const char* Abase = sm + (c & 1) * AS_ST;
        const char* Hbase = sm + SM_BH + (c & 1) * BH_ST;
        const char* Lbase = sm + SM_BL + (c & 1) * BH_ST;
        #pragma unroll
        for (int ki = 0; ki < 4; ki++) {
            const int ks = ki * 16;
            unsigned a[2][4];
            #pragma unroll
            for (int mt = 0; mt < 2; mt++) {
                const __half* ap = (const __half*)(Abase + (wm * 32 + mt * 16 + g) * SROW) + ks + tig * 2;
                a[mt][0] = *(const unsigned*)(ap);
                a[mt][1] = *(const unsigned*)(ap + 8 * 72);
                a[mt][2] = *(const unsigned*)(ap + 8);
                a[mt][3] = *(const unsigned*)(ap + 8 * 72 + 8);
            }
            #pragma unroll
            for (int nt = 0; nt < 8; nt++) {
                int n = wn * 64 + nt * 8 + g;
                const __half* bph = (const __half*)(Hbase + n * SROW) + ks + tig * 2;
                const __half* bpl = (const __half*)(Lbase + n * SROW) + ks + tig * 2;
                unsigned bh0 = *(const unsigned*)(bph);
                unsigned bh1 = *(const unsigned*)(bph + 8);
                unsigned bl0 = *(const unsigned*)(bpl);
                unsigned bl1 = *(const unsigned*)(bpl + 8);
                #pragma unroll
                for (int mt = 0; mt < 2; mt++) {
                    asm volatile(
                        "mma.sync.aligned.m16n8k16.row.col.f32.f16.f16.f32 "
                        "{%0,%1,%2,%3}, {%4,%5,%6,%7}, {%8,%9}, {%0,%1,%2,%3};\n"
                        : "+f"(acc[mt][nt][0]), "+f"(acc[mt][nt][1]),
                          "+f"(acc[mt][nt][2]), "+f"(acc[mt][nt][3])
                        : "r"(a[mt][0]), "r"(a[mt][1]), "r"(a[mt][2]), "r"(a[mt][3]),
                          "r"(bh0), "r"(bh1));
                    asm volatile(
                        "mma.sync.aligned.m16n8k16.row.col.f32.f16.f16.f32 "
                        "{%0,%1,%2,%3}, {%4,%5,%6,%7}, {%8,%9}, {%0,%1,%2,%3};\n"
                        : "+f"(acc[mt][nt][0]), "+f"(acc[mt][nt][1]),
                          "+f"(acc[mt][nt][2]), "+f"(acc[mt][nt][3])
                        : "r"(a[mt][0]), "r"(a[mt][1]), "r"(a[mt][2]), "r"(a[mt][3]),
                          "r"(bl0), "r"(bl1));
                }
            }
        }
        __syncthreads();
    }

    // epilogue: store y + column sum/sumsq
    #pragma unroll
    for (int nt = 0; nt < 8; nt++) {
        int col = wn * 64 + nt * 8 + tig * 2;
        float s0 = 0.f, s1 = 0.f, q0 = 0.f, q1 = 0.f;
        #pragma unroll
        for (int mt = 0; mt < 2; mt++) {
            float c0 = acc[mt][nt][0], c1 = acc[mt][nt][1];
            float c2 = acc[mt][nt][2], c3 = acc[mt][nt][3];
            int r = i0 + wm * 32 + mt * 16 + g;
            *(float2*)(d_y + (size_t)r * F2DIM + col)       = make_float2(c0, c1);
            *(float2*)(d_y + (size_t)(r + 8) * F2DIM + col) = make_float2(c2, c3);
            s0 += c0 + c2;  s1 += c1 + c3;
            q0 += c0 * c0 + c2 * c2;  q1 += c1 * c1 + c3 * c3;
        }
        #pragma unroll
        for (int off = 4; off < 32; off <<= 1) {
            s0 += __shfl_xor_sync(0xffffffffu, s0, off);
            s1 += __shfl_xor_sync(0xffffffffu, s1, off);
            q0 += __shfl_xor_sync(0xffffffffu, q0, off);
            q1 += __shfl_xor_sync(0xffffffffu, q1, off);
        }
        if (lane < 4) {
            atomicAdd(&colsum[col], s0);
            atomicAdd(&colsum[col + 1], s1);
            atomicAdd(&colsq[col], q0);
            atomicAdd(&colsq[col + 1], q1);
        }
    }
    __syncthreads();
    if (tid < 256) atomicAdd(&d_sum4[tid], colsum[tid]);
    else atomicAdd(&d_sq4[tid - 256], colsq[tid - 256]);
}

// ---------------- kernel 6: BN4 + relu + W5 dot -> logits ----------------
__global__ void __launch_bounds__(256) k_final(
    const float* __restrict__ g4, const float* __restrict__ be4,
    const float* __restrict__ W5, const float* __restrict__ b5,
    float* __restrict__ out)
{
    const int lane = threadIdx.x & 31;
    const int wid  = threadIdx.x >> 5;
    float a[8], c[8], w[8];
    #pragma unroll
    for (int j = 0; j < 8; j++) {
        int col = lane * 8 + j;
        float m  = d_sum4[col] * (1.0f / BATCH);
        float v  = d_sq4[col] * (1.0f / BATCH) - m * m;
        float aa = g4[col] * rsqrtf(v + EPS_F);
        a[j] = aa;
        c[j] = be4[col] - aa * m;
        w[j] = W5[col];
    }
    float bias = b5[0];
    for (int i = blockIdx.x * 8 + wid; i < BATCH; i += gridDim.x * 8) {
        const float4* yp = (const float4*)(d_y + (size_t)i * F2DIM + lane * 8);
        float4 v0 = yp[0];
        float4 v1 = yp[1];
        float accv =
            fmaxf(fmaf(a[0], v0.x, c[0]), 0.f) * w[0] +
            fmaxf(fmaf(a[1], v0.y, c[1]), 0.f) * w[1] +
            fmaxf(fmaf(a[2], v0.z, c[2]), 0.f) * w[2] +
            fmaxf(fmaf(a[3], v0.w, c[3]), 0.f) * w[3] +
            fmaxf(fmaf(a[4], v1.x, c[4]), 0.f) * w[4] +
            fmaxf(fmaf(a[5], v1.y, c[5]), 0.f) * w[5] +
            fmaxf(fmaf(a[6], v1.z, c[6]), 0.f) * w[6] +
            fmaxf(fmaf(a[7], v1.w, c[7]), 0.f) * w[7];
        #pragma unroll
        for (int off = 16; off; off >>= 1)
            accv += __shfl_xor_sync(0xffffffffu, accv, off);
        if (lane == 0) out[i] = accv + bias;
    }
}

// ---------------- launch ----------------
extern "C" void kernel_launch(void* const* d_in, const int* in_sizes, int n_in,
                              void* d_out, int out_size)
{
    (void)in_sizes; (void)n_in; (void)out_size;
    const int*   subj  = (const int*)d_in[0];
    const int*   obj   = (const int*)d_in[1];
    const int*   predi = (const int*)d_in[2];
    const float* W1    = (const float*)d_in[3];
    const float* g1    = (const float*)d_in[5];
    const float* be1   = (const float*)d_in[6];
    const float* W2    = (const float*)d_in[7];
    const float* g2    = (const float*)d_in[9];
    const float* be2   = (const float*)d_in[10];
    const float* W3    = (const float*)d_in[11];
    const float* g3    = (const float*)d_in[13];
    const float* be3   = (const float*)d_in[14];
    const float* W4    = (const float*)d_in[15];
    const float* g4    = (const float*)d_in[17];
    const float* be4   = (const float*)d_in[18];
    const float* W5    = (const float*)d_in[19];
    const float* b5    = (const float*)d_in[20];
    float* out = (float*)d_out;

    cudaFuncSetAttribute(k_gemm, cudaFuncAttributeMaxDynamicSharedMemorySize, SM_TOT);

    k_zero<<<512, 256>>>(W4);                               // 0
    k_hist<<<BATCH / 256, 256>>>(subj, obj, predi);         // 1
    k_compact<<<(OBJ_DIM + 255) / 256, 256>>>();            // 2
    k_cs<<<2220, 128>>>(W1, W2, W3, 1110, 2184);            // 3 : all three tables
    k_gather<<<BATCH / 32, 256>>>(subj, obj, predi, W1, W2, W3,
                                  g1, be1, g2, be2, g3, be3);  // 4
    k_gemm<<<BATCH / 128, 512, SM_TOT>>>();                 // 5  <- ncu -s 5 lands here
    k_final<<<2048, 256>>>(g4, be4, W5, b5, out);           // 6
}

// round 5
// speedup vs baseline: 2.6620x; 1.3347x over previous
#include <cuda_runtime.h>
#include <cuda_fp16.h>
#include <cstdint>
#include <cstddef>

#define BATCH     131072
#define FDIM      512
#define F2DIM     256
#define OBJ_DIM   100000
#define PRED_DIM  2000
#define EPS_F     1e-5f

// ---------------- device scratch (static, no allocation) ----------------
__device__ int   d_cnt_s[OBJ_DIM];
__device__ int   d_cnt_o[OBJ_DIM];
__device__ int   d_cnt_p[PRED_DIM + 8];
__device__ __align__(16) float d_sumb[3][FDIM];
__device__ __align__(16) float d_sqb [3][FDIM];
__device__ __align__(16) __half d_W4h[F2DIM * FDIM];         // fp16 W4, row-major [256][512]
__device__ __align__(16) __half d_Af[(size_t)BATCH * FDIM];  // fused fp16 A, 128 MB
__device__ __align__(16) __half d_yh[(size_t)BATCH * F2DIM]; // pre-BN layer-4 out, fp16, 64 MB
__device__ float d_sum4[F2DIM];
__device__ float d_sq4 [F2DIM];

// ---------------- helpers ----------------
__device__ __forceinline__ uint32_t smem_u32(const void* p) {
    uint32_t a;
    asm("{ .reg .u64 t; cvta.to.shared.u64 t, %1; cvt.u32.u64 %0, t; }" : "=r"(a) : "l"(p));
    return a;
}
__device__ __forceinline__ void cp16(uint32_t dst, const void* src) {
    asm volatile("cp.async.cg.shared.global [%0], [%1], 16;" :: "r"(dst), "l"(src) : "memory");
}
__device__ __forceinline__ void cp_commit() {
    asm volatile("cp.async.commit_group;" ::: "memory");
}
__device__ __forceinline__ float relu_aff(float a, float w, float c) {
    return fmaxf(fmaf(a, w, c), 0.f);
}

// ---------------- kernel 0: zero scratch + W4 -> fp16 ----------------
__global__ void __launch_bounds__(256) k_zero(const float* __restrict__ W4) {
    int i = blockIdx.x * blockDim.x + threadIdx.x;   // grid 512*256 = 131072
    if (i < OBJ_DIM) { d_cnt_s[i] = 0; d_cnt_o[i] = 0; }
    if (i < PRED_DIM + 8) d_cnt_p[i] = 0;
    if (i < FDIM) {
        #pragma unroll
        for (int b = 0; b < 3; b++) { d_sumb[b][i] = 0.f; d_sqb[b][i] = 0.f; }
    }
    if (i < F2DIM) { d_sum4[i] = 0.f; d_sq4[i] = 0.f; }
    d_W4h[i] = __float2half_rn(W4[i]);
}

// ---------------- kernel 1: index histograms ----------------
__global__ void k_hist(const int* __restrict__ subj, const int* __restrict__ obj,
                       const int* __restrict__ predi) {
    int i = blockIdx.x * blockDim.x + threadIdx.x;
    if (i < BATCH) {
        atomicAdd(&d_cnt_s[subj[i]], 1);
        atomicAdd(&d_cnt_o[obj[i]], 1);
        atomicAdd(&d_cnt_p[predi[i]], 1);
    }
}

// ---------------- kernel 2: count-weighted column stats (counts read inline) ----------------
__global__ void __launch_bounds__(128) k_cs(const float* __restrict__ W1,
                                            const float* __restrict__ W2,
                                            const float* __restrict__ W3,
                                            int S1, int S2) {
    const float* W; const int* cnt; int sel, bid, nblk, R;
    if ((int)blockIdx.x < S1)      { W = W1; cnt = d_cnt_s; sel = 0; bid = blockIdx.x;      nblk = S1;             R = OBJ_DIM; }
    else if ((int)blockIdx.x < S2) { W = W2; cnt = d_cnt_o; sel = 1; bid = blockIdx.x - S1; nblk = S2 - S1;        R = OBJ_DIM; }
    else                           { W = W3; cnt = d_cnt_p; sel = 2; bid = blockIdx.x - S2; nblk = gridDim.x - S2; R = PRED_DIM; }
    const int t = threadIdx.x;
    float4 s = make_float4(0.f, 0.f, 0.f, 0.f);
    float4 q = make_float4(0.f, 0.f, 0.f, 0.f);
    for (int base = bid * 8; base < R; base += nblk * 8) {
        int4 ca = *(const int4*)(cnt + base);
        int4 cb = *(const int4*)(cnt + base + 4);
        int cc[8] = {ca.x, ca.y, ca.z, ca.w, cb.x, cb.y, cb.z, cb.w};
        float4 v[8];
        #pragma unroll
        for (int u = 0; u < 8; u++)
            if (cc[u]) v[u] = __ldg((const float4*)(W + (size_t)(base + u) * FDIM) + t);
        #pragma unroll
        for (int u = 0; u < 8; u++) {
            if (cc[u]) {
                float fc = (float)cc[u];
                s.x += fc * v[u].x; s.y += fc * v[u].y; s.z += fc * v[u].z; s.w += fc * v[u].w;
                q.x += fc * v[u].x * v[u].x; q.y += fc * v[u].y * v[u].y;
                q.z += fc * v[u].z * v[u].z; q.w += fc * v[u].w * v[u].w;
            }
        }
    }
    int c0 = t * 4;
    atomicAdd(&d_sumb[sel][c0 + 0], s.x);
    atomicAdd(&d_sumb[sel][c0 + 1], s.y);
    atomicAdd(&d_sumb[sel][c0 + 2], s.z);
    atomicAdd(&d_sumb[sel][c0 + 3], s.w);
    atomicAdd(&d_sqb[sel][c0 + 0], q.x);
    atomicAdd(&d_sqb[sel][c0 + 1], q.y);
    atomicAdd(&d_sqb[sel][c0 + 2], q.z);
    atomicAdd(&d_sqb[sel][c0 + 3], q.w);
}

// ---------------- kernel 3: cp.async-pipelined gather + BN-relu -> fp16 A ----------------
// 64 rows/block, 16 stages of 4 rows, 3-stage smem ring. 256 threads.
#define G_ROWS   64
#define G_SR     4
#define G_NSTG   16
#define STG_B    (G_SR * 3 * FDIM * 4)        // 24576 bytes per stage
#define G_COEF   (3 * STG_B)                  // 73728
#define G_IDX    (G_COEF + 12288)             // 86016
#define G_SMEM   (G_IDX + 768)                // 86784

__global__ void __launch_bounds__(256) k_gather(
    const int* __restrict__ subj, const int* __restrict__ obj, const int* __restrict__ predi,
    const float* __restrict__ W1, const float* __restrict__ W2, const float* __restrict__ W3,
    const float* __restrict__ g1, const float* __restrict__ be1,
    const float* __restrict__ g2, const float* __restrict__ be2,
    const float* __restrict__ g3, const float* __restrict__ be3)
{
    extern __shared__ char sg[];
    const uint32_t smb = smem_u32(sg);
    float* cA = (float*)(sg + G_COEF);          // [3*512]
    float* cC = (float*)(sg + G_COEF + 6144);
    int*   idxs = (int*)(sg + G_IDX);           // [3][64]
    const int tid = threadIdx.x;
    const int i0 = blockIdx.x * G_ROWS;

    if (tid < G_ROWS) {
        idxs[tid]       = subj[i0 + tid];
        idxs[64 + tid]  = obj[i0 + tid];
        idxs[128 + tid] = predi[i0 + tid];
    }
    for (int t = tid; t < FDIM; t += 256) {
        float m, v, a;
        m = d_sumb[0][t] * (1.f / BATCH); v = d_sqb[0][t] * (1.f / BATCH) - m * m;
        a = g1[t] * rsqrtf(v + EPS_F); cA[t] = a;          cC[t] = be1[t] - a * m;
        m = d_sumb[1][t] * (1.f / BATCH); v = d_sqb[1][t] * (1.f / BATCH) - m * m;
        a = g2[t] * rsqrtf(v + EPS_F); cA[512 + t] = a;    cC[512 + t] = be2[t] - a * m;
        m = d_sumb[2][t] * (1.f / BATCH); v = d_sqb[2][t] * (1.f / BATCH) - m * m;
        a = g3[t] * rsqrtf(v + EPS_F); cA[1024 + t] = a;   cC[1024 + t] = be3[t] - a * m;
    }
    __syncthreads();

    // hoisted per-thread coef vectors (thread owns column group c4 forever)
    const int c4 = tid & 127;
    const int rs0 = tid >> 7;          // 0..1
    const int k0 = c4 * 4;
    const float4 A1 = *(const float4*)&cA[k0],        C1 = *(const float4*)&cC[k0];
    const float4 A2 = *(const float4*)&cA[512 + k0],  C2 = *(const float4*)&cC[512 + k0];
    const float4 A3 = *(const float4*)&cA[1024 + k0], C3 = *(const float4*)&cC[1024 + k0];

    auto issue = [&](int s) {
        int buf = s % 3;
        uint32_t dstb = smb + buf * STG_B;
        #pragma unroll
        for (int u = 0; u < 6; u++) {
            int lin = tid + 256 * u;            // 0..1535 float4 slots
            int ris = lin / 384;                // row in stage
            int rem = lin - ris * 384;
            int tab = rem >> 7;                 // table 0..2
            int cc  = rem & 127;                // float4 col
            int gi  = idxs[tab * 64 + s * G_SR + ris];
            const float* Wt = (tab == 0) ? W1 : (tab == 1) ? W2 : W3;
            cp16(dstb + lin * 16, Wt + (size_t)gi * FDIM + cc * 4);
        }
        cp_commit();
    };

    issue(0); issue(1);
    #pragma unroll 1
    for (int s = 0; s < G_NSTG; s++) {
        if (s + 2 < G_NSTG) issue(s + 2);
        if (s < G_NSTG - 2)       asm volatile("cp.async.wait_group 2;" ::: "memory");
        else if (s == G_NSTG - 2) asm volatile("cp.async.wait_group 1;" ::: "memory");
        else                      asm volatile("cp.async.wait_group 0;" ::: "memory");
        __syncthreads();
        const float4* st4 = (const float4*)(sg + (s % 3) * STG_B);
        #pragma unroll
        for (int rr = 0; rr < 2; rr++) {
            int ris = rs0 + rr * 2;
            int row = i0 + s * G_SR + ris;
            float4 w1 = st4[ris * 384 + c4];
            float4 w2 = st4[ris * 384 + 128 + c4];
            float4 w3 = st4[ris * 384 + 256 + c4];
            float f0 = relu_aff(A1.x, w1.x, C1.x) + relu_aff(A2.x, w2.x, C2.x) + relu_aff(A3.x, w3.x, C3.x);
            float f1 = relu_aff(A1.y, w1.y, C1.y) + relu_aff(A2.y, w2.y, C2.y) + relu_aff(A3.y, w3.y, C3.y);
            float f2 = relu_aff(A1.z, w1.z, C1.z) + relu_aff(A2.z, w2.z, C2.z) + relu_aff(A3.z, w3.z, C3.z);
            float f3 = relu_aff(A1.w, w1.w, C1.w) + relu_aff(A2.w, w2.w, C2.w) + relu_aff(A3.w, w3.w, C3.w);
            __half2 h0 = __floats2half2_rn(f0, f1);
            __half2 h1 = __floats2half2_rn(f2, f3);
            uint2 u;
            u.x = *(unsigned*)&h0;
            u.y = *(unsigned*)&h1;
            *(uint2*)(d_Af + (size_t)row * FDIM + k0) = u;
        }
        __syncthreads();
    }
}

// ---------------- kernel 4: GEMM y = A * W4^T (single fp16 B, cp.async pipelined) ----------------
#define KC      64
#define SROW    144                         // smem row stride bytes (72 halfs)
#define AS_ST   (128 * SROW)                // 18432 per stage
#define SM_BH   (2 * AS_ST)                 // 36864
#define BH_ST   (F2DIM * SROW)              // 36864 per stage
#define SM_SUM  (SM_BH + 2 * BH_ST)         // 110592
#define SM_SQ   (SM_SUM + 1024)
#define SM_TOT  (SM_SQ + 1024)              // 112640

__device__ __forceinline__ void gemm_issue(uint32_t smb, int i0, int c) {
    const int tid = threadIdx.x;
    const int s = c & 1;
    {
        const __half* Ag = d_Af + (size_t)i0 * FDIM + c * KC;
        #pragma unroll
        for (int u = 0; u < 2; u++) {
            int idx = tid + 512 * u;
            int row = idx >> 3, o = idx & 7;
            cp16(smb + s * AS_ST + row * SROW + o * 16, Ag + (size_t)row * FDIM + o * 8);
        }
    }
    #pragma unroll
    for (int u = 0; u < 4; u++) {
        int idx = tid + 512 * u;
        int n = idx >> 3, o = idx & 7;
        cp16(smb + SM_BH + s * BH_ST + n * SROW + o * 16, d_W4h + n * FDIM + c * KC + o * 8);
    }
    cp_commit();
}

__global__ void __launch_bounds__(512, 1) k_gemm() {
    extern __shared__ char sm[];
    const uint32_t smb = smem_u32(sm);
    const int tid = threadIdx.x, lane = tid & 31, wid = tid >> 5;
    const int i0 = blockIdx.x * 128;
    float* colsum = (float*)(sm + SM_SUM);
    float* colsq  = (float*)(sm + SM_SQ);
    if (tid < 256) colsum[tid] = 0.f;
    else colsq[tid - 256] = 0.f;

    const int wm = wid >> 2, wn = wid & 3, g = lane >> 2, tig = lane & 3;

    float acc[2][8][4];
    #pragma unroll
    for (int mt = 0; mt < 2; mt++)
        #pragma unroll
        for (int nt = 0; nt < 8; nt++)
            #pragma unroll
            for (int u = 0; u < 4; u++) acc[mt][nt][u] = 0.f;

    gemm_issue(smb, i0, 0);

    #pragma unroll 1
    for (int c = 0; c < 8; c++) {
        if (c < 7) {
            gemm_issue(smb, i0, c + 1);
            asm volatile("cp.async.wait_group 1;" ::: "memory");
        } else {
            asm volatile("cp.async.wait_group 0;" ::: "memory");
        }
        __syncthreads();
        const char* Abase = sm + (c & 1) * AS_ST;
        const char* Bbase = sm + SM_BH + (c & 1) * BH_ST;
        #pragma unroll
        for (int ki = 0; ki < 4; ki++) {
            const int ks = ki * 16;
            unsigned a[2][4];
            #pragma unroll
            for (int mt = 0; mt < 2; mt++) {
                const __half* ap = (const __half*)(Abase + (wm * 32 + mt * 16 + g) * SROW) + ks + tig * 2;
                a[mt][0] = *(const unsigned*)(ap);
                a[mt][1] = *(const unsigned*)(ap + 8 * 72);
                a[mt][2] = *(const unsigned*)(ap + 8);
                a[mt][3] = *(const unsigned*)(ap + 8 * 72 + 8);
            }
            #pragma unroll
            for (int nt = 0; nt < 8; nt++) {
                int n = wn * 64 + nt * 8 + g;
                const __half* bp = (const __half*)(Bbase + n * SROW) + ks + tig * 2;
                unsigned b0 = *(const unsigned*)(bp);
                unsigned b1 = *(const unsigned*)(bp + 8);
                #pragma unroll
                for (int mt = 0; mt < 2; mt++) {
                    asm volatile(
                        "mma.sync.aligned.m16n8k16.row.col.f32.f16.f16.f32 "
                        "{%0,%1,%2,%3}, {%4,%5,%6,%7}, {%8,%9}, {%0,%1,%2,%3};\n"
                        : "+f"(acc[mt][nt][0]), "+f"(acc[mt][nt][1]),
                          "+f"(acc[mt][nt][2]), "+f"(acc[mt][nt][3])
                        : "r"(a[mt][0]), "r"(a[mt][1]), "r"(a[mt][2]), "r"(a[mt][3]),
                          "r"(b0), "r"(b1));
                }
            }
        }
        __syncthreads();
    }

    // epilogue: store y (fp16) + column sum/sumsq (exact fp32 from accs)
    #pragma unroll
    for (int nt = 0; nt < 8; nt++) {
        int col = wn * 64 + nt * 8 + tig * 2;
        float s0 = 0.f, s1 = 0.f, q0 = 0.f, q1 = 0.f;
        #pragma unroll
        for (int mt = 0; mt < 2; mt++) {
            float c0 = acc[mt][nt][0], c1 = acc[mt][nt][1];
            float c2 = acc[mt][nt][2], c3 = acc[mt][nt][3];
            int r = i0 + wm * 32 + mt * 16 + g;
            *(__half2*)(d_yh + (size_t)r * F2DIM + col)       = __floats2half2_rn(c0, c1);
            *(__half2*)(d_yh + (size_t)(r + 8) * F2DIM + col) = __floats2half2_rn(c2, c3);
            s0 += c0 + c2;  s1 += c1 + c3;
            q0 += c0 * c0 + c2 * c2;  q1 += c1 * c1 + c3 * c3;
        }
        #pragma unroll
        for (int off = 4; off < 32; off <<= 1) {
            s0 += __shfl_xor_sync(0xffffffffu, s0, off);
            s1 += __shfl_xor_sync(0xffffffffu, s1, off);
            q0 += __shfl_xor_sync(0xffffffffu, q0, off);
            q1 += __shfl_xor_sync(0xffffffffu, q1, off);
        }
        if (lane < 4) {
            atomicAdd(&colsum[col], s0);
            atomicAdd(&colsum[col + 1], s1);
            atomicAdd(&colsq[col], q0);
            atomicAdd(&colsq[col + 1], q1);
        }
    }
    __syncthreads();
    if (tid < 256) atomicAdd(&d_sum4[tid], colsum[tid]);
    else atomicAdd(&d_sq4[tid - 256], colsq[tid - 256]);
}

// ---------------- kernel 5: BN4 + relu + W5 dot -> logits ----------------
__global__ void __launch_bounds__(256) k_final(
    const float* __restrict__ g4, const float* __restrict__ be4,
    const float* __restrict__ W5, const float* __restrict__ b5,
    float* __restrict__ out)
{
    const int lane = threadIdx.x & 31;
    const int wid  = threadIdx.x >> 5;
    float a[8], c[8], w[8];
    #pragma unroll
    for (int j = 0; j < 8; j++) {
        int col = lane * 8 + j;
        float m  = d_sum4[col] * (1.0f / BATCH);
        float v  = d_sq4[col] * (1.0f / BATCH) - m * m;
        float aa = g4[col] * rsqrtf(v + EPS_F);
        a[j] = aa;
        c[j] = be4[col] - aa * m;
        w[j] = W5[col];
    }
    float bias = b5[0];
    for (int i = blockIdx.x * 8 + wid; i < BATCH; i += gridDim.x * 8) {
        uint4 raw = *(const uint4*)(d_yh + (size_t)i * F2DIM + lane * 8);
        float2 f0 = __half22float2(*(__half2*)&raw.x);
        float2 f1 = __half22float2(*(__half2*)&raw.y);
        float2 f2 = __half22float2(*(__half2*)&raw.z);
        float2 f3 = __half22float2(*(__half2*)&raw.w);
        float accv =
            fmaxf(fmaf(a[0], f0.x, c[0]), 0.f) * w[0] +
            fmaxf(fmaf(a[1], f0.y, c[1]), 0.f) * w[1] +
            fmaxf(fmaf(a[2], f1.x, c[2]), 0.f) * w[2] +
            fmaxf(fmaf(a[3], f1.y, c[3]), 0.f) * w[3] +
            fmaxf(fmaf(a[4], f2.x, c[4]), 0.f) * w[4] +
            fmaxf(fmaf(a[5], f2.y, c[5]), 0.f) * w[5] +
            fmaxf(fmaf(a[6], f3.x, c[6]), 0.f) * w[6] +
            fmaxf(fmaf(a[7], f3.y, c[7]), 0.f) * w[7];
        #pragma unroll
        for (int off = 16; off; off >>= 1)
            accv += __shfl_xor_sync(0xffffffffu, accv, off);
        if (lane == 0) out[i] = accv + bias;
    }
}

// ---------------- launch ----------------
extern "C" void kernel_launch(void* const* d_in, const int* in_sizes, int n_in,
                              void* d_out, int out_size)
{
    (void)in_sizes; (void)n_in; (void)out_size;
    const int*   subj  = (const int*)d_in[0];
    const int*   obj   = (const int*)d_in[1];
    const int*   predi = (const int*)d_in[2];
    const float* W1    = (const float*)d_in[3];
    const float* g1    = (const float*)d_in[5];
    const float* be1   = (const float*)d_in[6];
    const float* W2    = (const float*)d_in[7];
    const float* g2    = (const float*)d_in[9];
    const float* be2   = (const float*)d_in[10];
    const float* W3    = (const float*)d_in[11];
    const float* g3    = (const float*)d_in[13];
    const float* be3   = (const float*)d_in[14];
    const float* W4    = (const float*)d_in[15];
    const float* g4    = (const float*)d_in[17];
    const float* be4   = (const float*)d_in[18];
    const float* W5    = (const float*)d_in[19];
    const float* b5    = (const float*)d_in[20];
    float* out = (float*)d_out;

    cudaFuncSetAttribute(k_gather, cudaFuncAttributeMaxDynamicSharedMemorySize, G_SMEM);
    cudaFuncSetAttribute(k_gemm, cudaFuncAttributeMaxDynamicSharedMemorySize, SM_TOT);

    k_zero<<<512, 256>>>(W4);                               // 0
    k_hist<<<BATCH / 256, 256>>>(subj, obj, predi);         // 1
    k_cs<<<1792, 128>>>(W1, W2, W3, 864, 1728);             // 2
    k_gather<<<BATCH / G_ROWS, 256, G_SMEM>>>(subj, obj, predi, W1, W2, W3,
                                              g1, be1, g2, be2, g3, be3);  // 3 <- profile target
    k_gemm<<<BATCH / 128, 512, SM_TOT>>>();                 // 4
    k_final<<<2048, 256>>>(g4, be4, W5, b5, out);           // 5
}